// round 2
// baseline (speedup 1.0000x reference)
#include <cuda_runtime.h>
#include <cuda_bf16.h>
#include <math.h>

// ---------------- problem constants ----------------
#define BATCH   64          // Bw (= num_windows * batch), also == nW here
#define NSEQ    343         // window volume 7*7*7
#define DIMC    384
#define NHEADS  12
#define HD      32
#define KDIM    384
#define QKV_N   1152
#define TABSZ   2197        // 13*13*13
#define CPBH    512

// ---------------- scratch (device globals; no runtime alloc allowed) ------
__device__ float g_Q[(size_t)BATCH * NHEADS * NSEQ * HD];
__device__ float g_K[(size_t)BATCH * NHEADS * NSEQ * HD];
__device__ float g_V[(size_t)BATCH * NHEADS * NSEQ * HD];
__device__ float g_O[(size_t)BATCH * NSEQ * DIMC];
__device__ float g_bias[(size_t)NHEADS * NSEQ * NSEQ];
__device__ float g_tableH[(size_t)TABSZ * NHEADS];

// ---------------- helpers ----------------
__device__ __forceinline__ float warpSum(float v) {
    #pragma unroll
    for (int o = 16; o > 0; o >>= 1) v += __shfl_xor_sync(0xffffffffu, v, o);
    return v;
}
__device__ __forceinline__ float warpMax(float v) {
    #pragma unroll
    for (int o = 16; o > 0; o >>= 1) v = fmaxf(v, __shfl_xor_sync(0xffffffffu, v, o));
    return v;
}

// ---------------- kernel 1: CPB MLP -> per-table-entry head bias ----------
__global__ void cpb_table_kernel(const float* __restrict__ tab,
                                 const float* __restrict__ w1,
                                 const float* __restrict__ b1,
                                 const float* __restrict__ w2) {
    __shared__ float hid[CPBH];
    int r = blockIdx.x;
    int tid = threadIdx.x;
    float t0 = tab[r * 3 + 0], t1 = tab[r * 3 + 1], t2 = tab[r * 3 + 2];
    float h = fmaf(w1[tid * 3 + 0], t0,
              fmaf(w1[tid * 3 + 1], t1,
              fmaf(w1[tid * 3 + 2], t2, b1[tid])));
    hid[tid] = fmaxf(h, 0.f);
    __syncthreads();
    int warp = tid >> 5, lane = tid & 31;
    if (warp < NHEADS) {
        float s = 0.f;
        #pragma unroll
        for (int j = lane; j < CPBH; j += 32) s = fmaf(hid[j], w2[warp * CPBH + j], s);
        s = warpSum(s);
        if (lane == 0) g_tableH[r * NHEADS + warp] = s;
    }
}

// ---------------- kernel 2: gather -> (H, N, N) bias with 16*sigmoid -----
__global__ void bias_gather_kernel(const int* __restrict__ idx) {
    int t = blockIdx.x * blockDim.x + threadIdx.x;
    const int NN = NSEQ * NSEQ;
    if (t >= NHEADS * NN) return;
    int h = t / NN;
    int ij = t - h * NN;
    float v = g_tableH[idx[ij] * NHEADS + h];
    g_bias[t] = 16.f / (1.f + __expf(-v));
}

// ---------------- kernel 3/5: sgemm, 128x64x16, 8x4 per thread -----------
// MODE 0: QKV — A is the harness x pointer; scatter into g_Q/g_K/g_V with
//         concat(q_bias, 0, v_bias)
// MODE 1: proj — A is the device-global g_O (referenced IN DEVICE CODE;
//         passing a __device__ symbol from host silently binds the host
//         shadow on GB300/ATS and reads zeros) ; Cout = acc + bias0[o]
#define BM 128
#define BN 64
#define BKK 16
#define TM 8
#define TN 4

template <int MODE>
__global__ void __launch_bounds__(256, 2)
sgemm_kernel(const float* __restrict__ A_in, const float* __restrict__ B,
             const float* __restrict__ bias0, const float* __restrict__ bias1,
             float* __restrict__ Cout, int M) {
    const float* __restrict__ A = (MODE == 1) ? (const float*)g_O : A_in;

    __shared__ float sA[BKK][BM];
    __shared__ float sB[BKK][BN];

    int tid = threadIdx.x;
    int tx = tid & 15;       // 0..15  -> col block (TN=4)
    int ty = tid >> 4;       // 0..15  -> row block (TM=8)
    int bm = blockIdx.x * BM;
    int bn = blockIdx.y * BN;

    float acc[TM][TN];
    #pragma unroll
    for (int i = 0; i < TM; i++)
        #pragma unroll
        for (int j = 0; j < TN; j++) acc[i][j] = 0.f;

    for (int k0 = 0; k0 < KDIM; k0 += BKK) {
        // load A tile (128 x 16): 512 float4, 2 per thread, transposed store
        #pragma unroll
        for (int l = 0; l < 2; l++) {
            int f = tid + l * 256;
            int row = f >> 2;
            int kc = (f & 3) * 4;
            float4 v = make_float4(0.f, 0.f, 0.f, 0.f);
            if (bm + row < M)
                v = *(const float4*)(A + (size_t)(bm + row) * KDIM + k0 + kc);
            sA[kc + 0][row] = v.x; sA[kc + 1][row] = v.y;
            sA[kc + 2][row] = v.z; sA[kc + 3][row] = v.w;
        }
        // load B tile (64 x 16 from row-major W[N][K]): 256 float4, 1 per thread
        {
            int n = tid >> 2;
            int kc = (tid & 3) * 4;
            float4 v = *(const float4*)(B + (size_t)(bn + n) * KDIM + k0 + kc);
            sB[kc + 0][n] = v.x; sB[kc + 1][n] = v.y;
            sB[kc + 2][n] = v.z; sB[kc + 3][n] = v.w;
        }
        __syncthreads();

        #pragma unroll
        for (int kk = 0; kk < BKK; kk++) {
            float4 a0 = *(const float4*)&sA[kk][ty * TM + 0];
            float4 a1 = *(const float4*)&sA[kk][ty * TM + 4];
            float4 b0 = *(const float4*)&sB[kk][tx * TN];
            float am[TM] = {a0.x, a0.y, a0.z, a0.w, a1.x, a1.y, a1.z, a1.w};
            float bb[TN] = {b0.x, b0.y, b0.z, b0.w};
            #pragma unroll
            for (int i = 0; i < TM; i++)
                #pragma unroll
                for (int j = 0; j < TN; j++) acc[i][j] = fmaf(am[i], bb[j], acc[i][j]);
        }
        __syncthreads();
    }

    // epilogue
    #pragma unroll
    for (int i = 0; i < TM; i++) {
        int m = bm + ty * TM + i;
        if (m >= M) continue;
        #pragma unroll
        for (int j = 0; j < TN; j++) {
            int o = bn + tx * TN + j;
            if (MODE == 0) {
                int part = o / DIMC;          // 0=q 1=k 2=v (constant per block)
                int oc = o - part * DIMC;
                int hh = oc >> 5, d = oc & 31;
                float b = (part == 0) ? bias0[oc] : (part == 2 ? bias1[oc] : 0.f);
                float val = acc[i][j] + b;
                int bw = m / NSEQ, nn = m - bw * NSEQ;
                size_t dst = ((size_t)(bw * NHEADS + hh) * NSEQ + nn) * HD + d;
                if (part == 0)      g_Q[dst] = val;
                else if (part == 1) g_K[dst] = val;
                else                g_V[dst] = val;
            } else {
                Cout[(size_t)m * DIMC + o] = acc[i][j] + bias0[o];
            }
        }
    }
}

// ---------------- kernel 4: windowed attention -----------------------------
// One block per (query-tile of 64, head, window). smem: Q(64x33), K(343x33),
// V(343x33), S(64x344). fp32 throughout.
#define QT 64
#define SQ_STRIDE 33
#define SS_STRIDE 344
#define SMEM_FLOATS (QT * SQ_STRIDE + 2 * (NSEQ * SQ_STRIDE) + QT * SS_STRIDE)

__global__ void __launch_bounds__(256, 1)
attn_kernel(const float* __restrict__ mask, const float* __restrict__ logit_scale) {
    extern __shared__ float smem[];
    float* sQ = smem;                            // 64*33
    float* sK = sQ + QT * SQ_STRIDE;             // 343*33
    float* sV = sK + NSEQ * SQ_STRIDE;           // 343*33
    float* sS = sV + NSEQ * SQ_STRIDE;           // 64*344

    int qbase = blockIdx.x * QT;
    int h = blockIdx.y;
    int bw = blockIdx.z;
    int tid = threadIdx.x;
    int warp = tid >> 5, lane = tid & 31;

    int qrows = min(QT, NSEQ - qbase);
    size_t headBase = ((size_t)(bw * NHEADS + h) * NSEQ) * HD;

    // ---- load K, V (full), Q (tile) ----
    const float* Kg = g_K + headBase;
    const float* Vg = g_V + headBase;
    const float* Qg = g_Q + headBase + (size_t)qbase * HD;
    for (int e4 = tid; e4 < NSEQ * 8; e4 += 256) {
        int r = e4 >> 3, d4 = (e4 & 7) * 4;
        float4 v = *(const float4*)(Kg + r * HD + d4);
        sK[r * SQ_STRIDE + d4 + 0] = v.x; sK[r * SQ_STRIDE + d4 + 1] = v.y;
        sK[r * SQ_STRIDE + d4 + 2] = v.z; sK[r * SQ_STRIDE + d4 + 3] = v.w;
        float4 w = *(const float4*)(Vg + r * HD + d4);
        sV[r * SQ_STRIDE + d4 + 0] = w.x; sV[r * SQ_STRIDE + d4 + 1] = w.y;
        sV[r * SQ_STRIDE + d4 + 2] = w.z; sV[r * SQ_STRIDE + d4 + 3] = w.w;
    }
    for (int e4 = tid; e4 < qrows * 8; e4 += 256) {
        int r = e4 >> 3, d4 = (e4 & 7) * 4;
        float4 v = *(const float4*)(Qg + r * HD + d4);
        sQ[r * SQ_STRIDE + d4 + 0] = v.x; sQ[r * SQ_STRIDE + d4 + 1] = v.y;
        sQ[r * SQ_STRIDE + d4 + 2] = v.z; sQ[r * SQ_STRIDE + d4 + 3] = v.w;
    }
    __syncthreads();

    // ---- cosine normalization (clip norm at 1e-12) ----
    for (int r = warp; r < NSEQ; r += 8) {
        float v = sK[r * SQ_STRIDE + lane];
        float s = warpSum(v * v);
        sK[r * SQ_STRIDE + lane] = v * (1.f / fmaxf(sqrtf(s), 1e-12f));
    }
    for (int r = warp; r < qrows; r += 8) {
        float v = sQ[r * SQ_STRIDE + lane];
        float s = warpSum(v * v);
        sQ[r * SQ_STRIDE + lane] = v * (1.f / fmaxf(sqrtf(s), 1e-12f));
    }
    __syncthreads();

    // ---- scores: S = scale * (Qn Kn^T) + cpb_bias + mask ----
    float scale = expf(fminf(logit_scale[h], 4.6051702f)); // ln(100)
    int tx = tid & 15;   // 4 cols each
    int ty = tid >> 4;   // 4 rows each
    for (int c0 = 0; c0 < NSEQ; c0 += 64) {
        float acc[4][4];
        #pragma unroll
        for (int i = 0; i < 4; i++)
            #pragma unroll
            for (int j = 0; j < 4; j++) acc[i][j] = 0.f;
        int cvalid[4];
        #pragma unroll
        for (int j = 0; j < 4; j++) cvalid[j] = (c0 + tx * 4 + j) < NSEQ;
        #pragma unroll 8
        for (int d = 0; d < HD; d++) {
            float qv[4], kv[4];
            #pragma unroll
            for (int i = 0; i < 4; i++) qv[i] = sQ[(ty * 4 + i) * SQ_STRIDE + d];
            #pragma unroll
            for (int j = 0; j < 4; j++)
                kv[j] = cvalid[j] ? sK[(c0 + tx * 4 + j) * SQ_STRIDE + d] : 0.f;
            #pragma unroll
            for (int i = 0; i < 4; i++)
                #pragma unroll
                for (int j = 0; j < 4; j++) acc[i][j] = fmaf(qv[i], kv[j], acc[i][j]);
        }
        #pragma unroll
        for (int i = 0; i < 4; i++) {
            int r = ty * 4 + i;
            int gi = qbase + r;
            if (gi >= NSEQ) continue;
            #pragma unroll
            for (int j = 0; j < 4; j++) {
                int gj = c0 + tx * 4 + j;
                if (gj >= NSEQ) continue;
                float b = g_bias[((size_t)h * NSEQ + gi) * NSEQ + gj];
                float mk = mask[((size_t)bw * NSEQ + gi) * NSEQ + gj];
                sS[r * SS_STRIDE + gj] = fmaf(acc[i][j], scale, b + mk);
            }
        }
    }
    __syncthreads();

    // ---- softmax over rows ----
    for (int r = warp; r < QT; r += 8) {
        if (qbase + r >= NSEQ) continue;
        float* row = sS + r * SS_STRIDE;
        float m = -1e30f;
        for (int j = lane; j < NSEQ; j += 32) m = fmaxf(m, row[j]);
        m = warpMax(m);
        float sum = 0.f;
        for (int j = lane; j < NSEQ; j += 32) {
            float p = __expf(row[j] - m);
            row[j] = p;
            sum += p;
        }
        sum = warpSum(sum);
        float inv = 1.f / sum;
        for (int j = lane; j < NSEQ; j += 32) row[j] *= inv;
    }
    __syncthreads();

    // ---- O = P @ V (64 x 32) ----
    {
        int cx = tid & 15;   // 2 cols each
        int ry = tid >> 4;   // 4 rows each
        float acc[4][2];
        #pragma unroll
        for (int i = 0; i < 4; i++) { acc[i][0] = 0.f; acc[i][1] = 0.f; }
        for (int j = 0; j < NSEQ; j++) {
            float v0 = sV[j * SQ_STRIDE + cx * 2 + 0];
            float v1 = sV[j * SQ_STRIDE + cx * 2 + 1];
            #pragma unroll
            for (int i = 0; i < 4; i++) {
                float p = sS[(ry * 4 + i) * SS_STRIDE + j];
                acc[i][0] = fmaf(p, v0, acc[i][0]);
                acc[i][1] = fmaf(p, v1, acc[i][1]);
            }
        }
        #pragma unroll
        for (int i = 0; i < 4; i++) {
            int gi = qbase + ry * 4 + i;
            if (gi >= NSEQ) continue;
            float* dst = g_O + ((size_t)bw * NSEQ + gi) * DIMC + h * HD + cx * 2;
            dst[0] = acc[i][0];
            dst[1] = acc[i][1];
        }
    }
}

// ---------------- launch -----------------------------------------------------
extern "C" void kernel_launch(void* const* d_in, const int* in_sizes, int n_in,
                              void* d_out, int out_size) {
    const float* x        = (const float*)d_in[0];
    const float* mask     = (const float*)d_in[1];
    const float* qkv_w    = (const float*)d_in[2];
    const float* q_bias   = (const float*)d_in[3];
    const float* v_bias   = (const float*)d_in[4];
    const float* lscale   = (const float*)d_in[5];
    const float* cpb_w1   = (const float*)d_in[6];
    const float* cpb_b1   = (const float*)d_in[7];
    const float* cpb_w2   = (const float*)d_in[8];
    const float* proj_w   = (const float*)d_in[9];
    const float* proj_b   = (const float*)d_in[10];
    const float* rel_tab  = (const float*)d_in[11];
    const int*   rel_idx  = (const int*)d_in[12];
    float* out = (float*)d_out;

    const int M = BATCH * NSEQ;   // 21952

    // 1) CPB MLP
    cpb_table_kernel<<<TABSZ, CPBH>>>(rel_tab, cpb_w1, cpb_b1, cpb_w2);

    // 2) bias gather
    {
        int total = NHEADS * NSEQ * NSEQ;
        bias_gather_kernel<<<(total + 255) / 256, 256>>>(rel_idx);
    }

    // 3) QKV GEMM + scatter
    {
        dim3 grid((M + BM - 1) / BM, QKV_N / BN);
        sgemm_kernel<0><<<grid, 256>>>(x, qkv_w, q_bias, v_bias, nullptr, M);
    }

    // 4) attention
    {
        static const size_t smemBytes = (size_t)SMEM_FLOATS * sizeof(float);
        cudaFuncSetAttribute(attn_kernel,
                             cudaFuncAttributeMaxDynamicSharedMemorySize,
                             (int)smemBytes);
        dim3 grid((NSEQ + QT - 1) / QT, NHEADS, BATCH);
        attn_kernel<<<grid, 256, smemBytes>>>(mask, lscale);
    }

    // 5) projection GEMM (A = g_O referenced in device code, NOT passed from host)
    {
        dim3 grid((M + BM - 1) / BM, DIMC / BN);
        sgemm_kernel<1><<<grid, 256>>>(nullptr, proj_w, proj_b, nullptr, out, M);
    }
}

// round 3
// speedup vs baseline: 1.3509x; 1.3509x over previous
#include <cuda_runtime.h>
#include <cuda_bf16.h>
#include <math.h>

// ---------------- problem constants ----------------
#define BATCH   64
#define NSEQ    343
#define DIMC    384
#define NHEADS  12
#define HD      32
#define KDIM    384
#define QKV_N   1152
#define TABSZ   2197
#define CPBH    512

// ---------------- scratch ----------------
__device__ float g_Q[(size_t)BATCH * NHEADS * NSEQ * HD];
__device__ float g_K[(size_t)BATCH * NHEADS * NSEQ * HD];
__device__ float g_V[(size_t)BATCH * NHEADS * NSEQ * HD];
__device__ float g_O[(size_t)BATCH * NSEQ * DIMC];
__device__ float g_bias[(size_t)NHEADS * NSEQ * NSEQ];
__device__ float g_tableH[(size_t)TABSZ * NHEADS];

__device__ __forceinline__ float warpSum(float v) {
    #pragma unroll
    for (int o = 16; o > 0; o >>= 1) v += __shfl_xor_sync(0xffffffffu, v, o);
    return v;
}
__device__ __forceinline__ float warpMax(float v) {
    #pragma unroll
    for (int o = 16; o > 0; o >>= 1) v = fmaxf(v, __shfl_xor_sync(0xffffffffu, v, o));
    return v;
}

// ---------------- kernel 1: CPB MLP ----------------
__global__ void cpb_table_kernel(const float* __restrict__ tab,
                                 const float* __restrict__ w1,
                                 const float* __restrict__ b1,
                                 const float* __restrict__ w2) {
    __shared__ float hid[CPBH];
    int r = blockIdx.x;
    int tid = threadIdx.x;
    float t0 = tab[r * 3 + 0], t1 = tab[r * 3 + 1], t2 = tab[r * 3 + 2];
    float h = fmaf(w1[tid * 3 + 0], t0,
              fmaf(w1[tid * 3 + 1], t1,
              fmaf(w1[tid * 3 + 2], t2, b1[tid])));
    hid[tid] = fmaxf(h, 0.f);
    __syncthreads();
    int warp = tid >> 5, lane = tid & 31;
    if (warp < NHEADS) {
        float s = 0.f;
        #pragma unroll
        for (int j = lane; j < CPBH; j += 32) s = fmaf(hid[j], w2[warp * CPBH + j], s);
        s = warpSum(s);
        if (lane == 0) g_tableH[r * NHEADS + warp] = s;
    }
}

// ---------------- kernel 2: bias gather ----------------
__global__ void bias_gather_kernel(const int* __restrict__ idx) {
    int t = blockIdx.x * blockDim.x + threadIdx.x;
    const int NN = NSEQ * NSEQ;
    if (t >= NHEADS * NN) return;
    int h = t / NN;
    int ij = t - h * NN;
    float v = g_tableH[idx[ij] * NHEADS + h];
    g_bias[t] = 16.f / (1.f + __expf(-v));
}

// ---------------- kernel 3/5: sgemm 128x128x8, double-buffered ------------
// MODE 0: QKV (A = x), scatter epilogue into g_Q/g_K/g_V with qkv bias
// MODE 1: proj (A = g_O referenced in device code), Cout = acc + bias
#define BM 128
#define BN 128
#define BKK 8

template <int MODE>
__global__ void __launch_bounds__(256, 2)
sgemm_kernel(const float* __restrict__ A_in, const float* __restrict__ B,
             const float* __restrict__ bias0, const float* __restrict__ bias1,
             float* __restrict__ Cout, int M) {
    const float* __restrict__ A = (MODE == 1) ? (const float*)g_O : A_in;

    __shared__ float sA[2][BKK][BM];
    __shared__ float sB[2][BKK][BN];

    int tid = threadIdx.x;
    int tx = tid & 15;
    int ty = tid >> 4;
    int bm = blockIdx.x * BM;
    int bn = blockIdx.y * BN;

    int lrow = tid >> 1;            // 0..127
    int lk   = (tid & 1) * 4;       // 0 or 4

    float acc[8][8];
    #pragma unroll
    for (int i = 0; i < 8; i++)
        #pragma unroll
        for (int j = 0; j < 8; j++) acc[i][j] = 0.f;

    // prologue: load tile 0
    {
        float4 va = make_float4(0.f, 0.f, 0.f, 0.f);
        if (bm + lrow < M) va = *(const float4*)(A + (size_t)(bm + lrow) * KDIM + lk);
        float4 vb = *(const float4*)(B + (size_t)(bn + lrow) * KDIM + lk);
        sA[0][lk + 0][lrow] = va.x; sA[0][lk + 1][lrow] = va.y;
        sA[0][lk + 2][lrow] = va.z; sA[0][lk + 3][lrow] = va.w;
        sB[0][lk + 0][lrow] = vb.x; sB[0][lk + 1][lrow] = vb.y;
        sB[0][lk + 2][lrow] = vb.z; sB[0][lk + 3][lrow] = vb.w;
    }
    __syncthreads();

    int buf = 0;
    for (int k0 = 0; k0 < KDIM; k0 += BKK, buf ^= 1) {
        float4 va, vb;
        bool has_next = (k0 + BKK < KDIM);
        if (has_next) {
            va = make_float4(0.f, 0.f, 0.f, 0.f);
            if (bm + lrow < M)
                va = *(const float4*)(A + (size_t)(bm + lrow) * KDIM + k0 + BKK + lk);
            vb = *(const float4*)(B + (size_t)(bn + lrow) * KDIM + k0 + BKK + lk);
        }

        #pragma unroll
        for (int kk = 0; kk < BKK; kk++) {
            float4 a0 = *(const float4*)&sA[buf][kk][ty * 4];
            float4 a1 = *(const float4*)&sA[buf][kk][64 + ty * 4];
            float4 b0 = *(const float4*)&sB[buf][kk][tx * 4];
            float4 b1 = *(const float4*)&sB[buf][kk][64 + tx * 4];
            float ar[8] = {a0.x, a0.y, a0.z, a0.w, a1.x, a1.y, a1.z, a1.w};
            float bc[8] = {b0.x, b0.y, b0.z, b0.w, b1.x, b1.y, b1.z, b1.w};
            #pragma unroll
            for (int i = 0; i < 8; i++)
                #pragma unroll
                for (int j = 0; j < 8; j++) acc[i][j] = fmaf(ar[i], bc[j], acc[i][j]);
        }

        if (has_next) {
            int nb = buf ^ 1;
            sA[nb][lk + 0][lrow] = va.x; sA[nb][lk + 1][lrow] = va.y;
            sA[nb][lk + 2][lrow] = va.z; sA[nb][lk + 3][lrow] = va.w;
            sB[nb][lk + 0][lrow] = vb.x; sB[nb][lk + 1][lrow] = vb.y;
            sB[nb][lk + 2][lrow] = vb.z; sB[nb][lk + 3][lrow] = vb.w;
            __syncthreads();
        }
    }

    // epilogue
    #pragma unroll
    for (int ih = 0; ih < 2; ih++) {
        #pragma unroll
        for (int i = 0; i < 4; i++) {
            int m = bm + ih * 64 + ty * 4 + i;
            if (m >= M) continue;
            int ridx = ih * 4 + i;
            int bw = m / NSEQ, nn = m - bw * NSEQ;
            #pragma unroll
            for (int jh = 0; jh < 2; jh++) {
                int o = bn + jh * 64 + tx * 4;     // quad-aligned
                float4 v = make_float4(acc[ridx][jh * 4 + 0], acc[ridx][jh * 4 + 1],
                                       acc[ridx][jh * 4 + 2], acc[ridx][jh * 4 + 3]);
                if (MODE == 0) {
                    int part = o / DIMC;
                    int oc = o - part * DIMC;
                    int hh = oc >> 5, d = oc & 31;
                    if (part == 0) {
                        float4 b = *(const float4*)(bias0 + oc);
                        v.x += b.x; v.y += b.y; v.z += b.z; v.w += b.w;
                    } else if (part == 2) {
                        float4 b = *(const float4*)(bias1 + oc);
                        v.x += b.x; v.y += b.y; v.z += b.z; v.w += b.w;
                    }
                    size_t dst = ((size_t)(bw * NHEADS + hh) * NSEQ + nn) * HD + d;
                    float* tgt = (part == 0) ? g_Q : (part == 1 ? g_K : g_V);
                    *(float4*)(tgt + dst) = v;
                } else {
                    float4 b = *(const float4*)(bias0 + o);
                    v.x += b.x; v.y += b.y; v.z += b.z; v.w += b.w;
                    *(float4*)(Cout + (size_t)m * DIMC + o) = v;
                }
            }
        }
    }
}

// ---------------- kernel 4: windowed attention -----------------------------
// 512 threads / CTA; one CTA per (64-query tile, head, window).
// smem: sQ 64x36, sK 343x36, sVT 32x348 (V transposed), sS 64x344.
#define QT 64
#define QK_STR 36
#define VT_STR 348
#define SS_STR 344
#define ATTN_THREADS 512
#define SMEM_FLOATS (QT * QK_STR + NSEQ * QK_STR + HD * VT_STR + QT * SS_STR)

__global__ void __launch_bounds__(ATTN_THREADS, 1)
attn_kernel(const float* __restrict__ mask, const float* __restrict__ logit_scale) {
    extern __shared__ float smem[];
    float* sQ  = smem;                       // 64*36
    float* sK  = sQ + QT * QK_STR;           // 343*36
    float* sVT = sK + NSEQ * QK_STR;         // 32*348
    float* sS  = sVT + HD * VT_STR;          // 64*344

    int qbase = blockIdx.x * QT;
    int h  = blockIdx.y;
    int bw = blockIdx.z;
    int tid = threadIdx.x;
    int warp = tid >> 5, lane = tid & 31;
    int qrows = min(QT, NSEQ - qbase);
    size_t headBase = ((size_t)(bw * NHEADS + h) * NSEQ) * HD;

    const float* Kg = g_K + headBase;
    const float* Vg = g_V + headBase;
    const float* Qg = g_Q + headBase + (size_t)qbase * HD;

    // ---- loads ----
    for (int e4 = tid; e4 < NSEQ * 8; e4 += ATTN_THREADS) {
        int r = e4 >> 3, d4 = (e4 & 7) * 4;
        float4 v = *(const float4*)(Kg + r * HD + d4);
        sK[r * QK_STR + d4 + 0] = v.x; sK[r * QK_STR + d4 + 1] = v.y;
        sK[r * QK_STR + d4 + 2] = v.z; sK[r * QK_STR + d4 + 3] = v.w;
    }
    for (int e = tid; e < NSEQ * HD; e += ATTN_THREADS) {
        int j = e >> 5, d = e & 31;           // coalesced gmem read
        sVT[d * VT_STR + j] = Vg[e];          // 4-way-conflict STS (cheap)
    }
    if (tid < HD) sVT[tid * VT_STR + 343] = 0.f;   // pad col for float4 PV
    for (int e4 = tid; e4 < qrows * 8; e4 += ATTN_THREADS) {
        int r = e4 >> 3, d4 = (e4 & 7) * 4;
        float4 v = *(const float4*)(Qg + r * HD + d4);
        sQ[r * QK_STR + d4 + 0] = v.x; sQ[r * QK_STR + d4 + 1] = v.y;
        sQ[r * QK_STR + d4 + 2] = v.z; sQ[r * QK_STR + d4 + 3] = v.w;
    }
    __syncthreads();

    // ---- cosine normalization ----
    for (int r = warp; r < NSEQ; r += 16) {
        float v = sK[r * QK_STR + lane];
        float s = warpSum(v * v);
        sK[r * QK_STR + lane] = v * (1.f / fmaxf(sqrtf(s), 1e-12f));
    }
    for (int r = warp; r < qrows; r += 16) {
        float v = sQ[r * QK_STR + lane];
        float s = warpSum(v * v);
        sQ[r * QK_STR + lane] = v * (1.f / fmaxf(sqrtf(s), 1e-12f));
    }
    __syncthreads();

    // ---- scores: S = scale * Qn Kn^T + bias + mask ----
    float scale = expf(fminf(logit_scale[h], 4.6051702f));
    {
        int tx = tid & 31;        // cols: c0+tx, c0+tx+32
        int ty = tid >> 5;        // rows: ty*4 .. ty*4+3
        for (int c0 = 0; c0 < NSEQ; c0 += 64) {
            float acc[4][2];
            #pragma unroll
            for (int i = 0; i < 4; i++) { acc[i][0] = 0.f; acc[i][1] = 0.f; }
            int col0 = c0 + tx, col1 = c0 + tx + 32;
            bool v0 = col0 < NSEQ, v1 = col1 < NSEQ;
            #pragma unroll
            for (int d4 = 0; d4 < HD; d4 += 4) {
                float4 k0 = v0 ? *(const float4*)&sK[col0 * QK_STR + d4]
                               : make_float4(0.f, 0.f, 0.f, 0.f);
                float4 k1 = v1 ? *(const float4*)&sK[col1 * QK_STR + d4]
                               : make_float4(0.f, 0.f, 0.f, 0.f);
                #pragma unroll
                for (int i = 0; i < 4; i++) {
                    float4 q = *(const float4*)&sQ[(ty * 4 + i) * QK_STR + d4];
                    acc[i][0] = fmaf(q.x, k0.x, acc[i][0]);
                    acc[i][0] = fmaf(q.y, k0.y, acc[i][0]);
                    acc[i][0] = fmaf(q.z, k0.z, acc[i][0]);
                    acc[i][0] = fmaf(q.w, k0.w, acc[i][0]);
                    acc[i][1] = fmaf(q.x, k1.x, acc[i][1]);
                    acc[i][1] = fmaf(q.y, k1.y, acc[i][1]);
                    acc[i][1] = fmaf(q.z, k1.z, acc[i][1]);
                    acc[i][1] = fmaf(q.w, k1.w, acc[i][1]);
                }
            }
            #pragma unroll
            for (int i = 0; i < 4; i++) {
                int gi = qbase + ty * 4 + i;
                if (gi >= NSEQ) continue;
                size_t bofs = ((size_t)h * NSEQ + gi) * NSEQ;
                size_t mofs = ((size_t)bw * NSEQ + gi) * NSEQ;
                if (v0)
                    sS[(ty * 4 + i) * SS_STR + col0] =
                        fmaf(acc[i][0], scale, g_bias[bofs + col0] + mask[mofs + col0]);
                if (v1)
                    sS[(ty * 4 + i) * SS_STR + col1] =
                        fmaf(acc[i][1], scale, g_bias[bofs + col1] + mask[mofs + col1]);
            }
        }
    }
    __syncthreads();

    // ---- softmax ----
    for (int r = warp; r < QT; r += 16) {
        if (qbase + r >= NSEQ) continue;
        float* row = sS + r * SS_STR;
        float m = -1e30f;
        for (int j = lane; j < NSEQ; j += 32) m = fmaxf(m, row[j]);
        m = warpMax(m);
        float sum = 0.f;
        for (int j = lane; j < NSEQ; j += 32) {
            float p = __expf(row[j] - m);
            row[j] = p;
            sum += p;
        }
        sum = warpSum(sum);
        float inv = 1.f / sum;
        for (int j = lane; j < NSEQ; j += 32) row[j] *= inv;
        if (lane == 0) row[343] = 0.f;         // pad for float4 PV
    }
    __syncthreads();

    // ---- O = P @ V : 64 x 32 ----
    {
        int cx = tid & 15;        // cols cx, cx+16
        int ry = tid >> 4;        // rows ry*2, ry*2+1
        float acc[2][2];
        acc[0][0] = acc[0][1] = acc[1][0] = acc[1][1] = 0.f;
        for (int j4 = 0; j4 < 344; j4 += 4) {
            float4 p0 = *(const float4*)&sS[(ry * 2 + 0) * SS_STR + j4];
            float4 p1 = *(const float4*)&sS[(ry * 2 + 1) * SS_STR + j4];
            float4 va = *(const float4*)&sVT[cx * VT_STR + j4];
            float4 vb = *(const float4*)&sVT[(cx + 16) * VT_STR + j4];
            acc[0][0] = fmaf(p0.x, va.x, acc[0][0]);
            acc[0][0] = fmaf(p0.y, va.y, acc[0][0]);
            acc[0][0] = fmaf(p0.z, va.z, acc[0][0]);
            acc[0][0] = fmaf(p0.w, va.w, acc[0][0]);
            acc[0][1] = fmaf(p0.x, vb.x, acc[0][1]);
            acc[0][1] = fmaf(p0.y, vb.y, acc[0][1]);
            acc[0][1] = fmaf(p0.z, vb.z, acc[0][1]);
            acc[0][1] = fmaf(p0.w, vb.w, acc[0][1]);
            acc[1][0] = fmaf(p1.x, va.x, acc[1][0]);
            acc[1][0] = fmaf(p1.y, va.y, acc[1][0]);
            acc[1][0] = fmaf(p1.z, va.z, acc[1][0]);
            acc[1][0] = fmaf(p1.w, va.w, acc[1][0]);
            acc[1][1] = fmaf(p1.x, vb.x, acc[1][1]);
            acc[1][1] = fmaf(p1.y, vb.y, acc[1][1]);
            acc[1][1] = fmaf(p1.z, vb.z, acc[1][1]);
            acc[1][1] = fmaf(p1.w, vb.w, acc[1][1]);
        }
        #pragma unroll
        for (int i = 0; i < 2; i++) {
            int gi = qbase + ry * 2 + i;
            if (gi >= NSEQ) continue;
            float* dst = g_O + ((size_t)bw * NSEQ + gi) * DIMC + h * HD;
            dst[cx] = acc[i][0];
            dst[cx + 16] = acc[i][1];
        }
    }
}

// ---------------- launch -----------------------------------------------------
extern "C" void kernel_launch(void* const* d_in, const int* in_sizes, int n_in,
                              void* d_out, int out_size) {
    const float* x        = (const float*)d_in[0];
    const float* mask     = (const float*)d_in[1];
    const float* qkv_w    = (const float*)d_in[2];
    const float* q_bias   = (const float*)d_in[3];
    const float* v_bias   = (const float*)d_in[4];
    const float* lscale   = (const float*)d_in[5];
    const float* cpb_w1   = (const float*)d_in[6];
    const float* cpb_b1   = (const float*)d_in[7];
    const float* cpb_w2   = (const float*)d_in[8];
    const float* proj_w   = (const float*)d_in[9];
    const float* proj_b   = (const float*)d_in[10];
    const float* rel_tab  = (const float*)d_in[11];
    const int*   rel_idx  = (const int*)d_in[12];
    float* out = (float*)d_out;

    const int M = BATCH * NSEQ;   // 21952

    cpb_table_kernel<<<TABSZ, CPBH>>>(rel_tab, cpb_w1, cpb_b1, cpb_w2);

    {
        int total = NHEADS * NSEQ * NSEQ;
        bias_gather_kernel<<<(total + 255) / 256, 256>>>(rel_idx);
    }

    {
        dim3 grid((M + BM - 1) / BM, QKV_N / BN);
        sgemm_kernel<0><<<grid, 256>>>(x, qkv_w, q_bias, v_bias, nullptr, M);
    }

    {
        static const size_t smemBytes = (size_t)SMEM_FLOATS * sizeof(float);
        cudaFuncSetAttribute(attn_kernel,
                             cudaFuncAttributeMaxDynamicSharedMemorySize,
                             (int)smemBytes);
        dim3 grid((NSEQ + QT - 1) / QT, NHEADS, BATCH);
        attn_kernel<<<grid, ATTN_THREADS, smemBytes>>>(mask, lscale);
    }

    {
        dim3 grid((M + BM - 1) / BM, DIMC / BN);
        sgemm_kernel<1><<<grid, 256>>>(nullptr, proj_w, proj_b, nullptr, out, M);
    }
}

// round 4
// speedup vs baseline: 1.3599x; 1.0066x over previous
#include <cuda_runtime.h>
#include <cuda_bf16.h>
#include <math.h>

// ---------------- problem constants ----------------
#define BATCH   64
#define NSEQ    343
#define DIMC    384
#define NHEADS  12
#define HD      32
#define KDIM    384
#define QKV_N   1152
#define TABSZ   2197
#define CPBH    512

// ---------------- scratch ----------------
__device__ float g_Q[(size_t)BATCH * NHEADS * NSEQ * HD];
__device__ float g_K[(size_t)BATCH * NHEADS * NSEQ * HD];
__device__ float g_V[(size_t)BATCH * NHEADS * NSEQ * HD];
__device__ float g_O[(size_t)BATCH * NSEQ * DIMC];
__device__ float g_bias[(size_t)NHEADS * NSEQ * NSEQ];
__device__ float g_tableH[(size_t)TABSZ * NHEADS];

__device__ __forceinline__ float warpSum(float v) {
    #pragma unroll
    for (int o = 16; o > 0; o >>= 1) v += __shfl_xor_sync(0xffffffffu, v, o);
    return v;
}
__device__ __forceinline__ float warpMax(float v) {
    #pragma unroll
    for (int o = 16; o > 0; o >>= 1) v = fmaxf(v, __shfl_xor_sync(0xffffffffu, v, o));
    return v;
}

// ---------------- kernel 1: CPB MLP ----------------
__global__ void cpb_table_kernel(const float* __restrict__ tab,
                                 const float* __restrict__ w1,
                                 const float* __restrict__ b1,
                                 const float* __restrict__ w2) {
    __shared__ float hid[CPBH];
    int r = blockIdx.x;
    int tid = threadIdx.x;
    float t0 = tab[r * 3 + 0], t1 = tab[r * 3 + 1], t2 = tab[r * 3 + 2];
    float h = fmaf(w1[tid * 3 + 0], t0,
              fmaf(w1[tid * 3 + 1], t1,
              fmaf(w1[tid * 3 + 2], t2, b1[tid])));
    hid[tid] = fmaxf(h, 0.f);
    __syncthreads();
    int warp = tid >> 5, lane = tid & 31;
    if (warp < NHEADS) {
        float s = 0.f;
        #pragma unroll
        for (int j = lane; j < CPBH; j += 32) s = fmaf(hid[j], w2[warp * CPBH + j], s);
        s = warpSum(s);
        if (lane == 0) g_tableH[r * NHEADS + warp] = s;
    }
}

// ---------------- kernel 2: bias gather ----------------
__global__ void bias_gather_kernel(const int* __restrict__ idx) {
    int t = blockIdx.x * blockDim.x + threadIdx.x;
    const int NN = NSEQ * NSEQ;
    if (t >= NHEADS * NN) return;
    int h = t / NN;
    int ij = t - h * NN;
    float v = g_tableH[idx[ij] * NHEADS + h];
    g_bias[t] = 16.f / (1.f + __expf(-v));
}

// ---------------- kernel 3/5: sgemm 128x128x8, double-buffered ------------
#define BM 128
#define BN 128
#define BKK 8

template <int MODE>
__global__ void __launch_bounds__(256, 2)
sgemm_kernel(const float* __restrict__ A_in, const float* __restrict__ B,
             const float* __restrict__ bias0, const float* __restrict__ bias1,
             float* __restrict__ Cout, int M) {
    const float* __restrict__ A = (MODE == 1) ? (const float*)g_O : A_in;

    __shared__ float sA[2][BKK][BM];
    __shared__ float sB[2][BKK][BN];

    int tid = threadIdx.x;
    int tx = tid & 15;
    int ty = tid >> 4;
    int bm = blockIdx.x * BM;
    int bn = blockIdx.y * BN;

    int lrow = tid >> 1;
    int lk   = (tid & 1) * 4;

    float acc[8][8];
    #pragma unroll
    for (int i = 0; i < 8; i++)
        #pragma unroll
        for (int j = 0; j < 8; j++) acc[i][j] = 0.f;

    {
        float4 va = make_float4(0.f, 0.f, 0.f, 0.f);
        if (bm + lrow < M) va = *(const float4*)(A + (size_t)(bm + lrow) * KDIM + lk);
        float4 vb = *(const float4*)(B + (size_t)(bn + lrow) * KDIM + lk);
        sA[0][lk + 0][lrow] = va.x; sA[0][lk + 1][lrow] = va.y;
        sA[0][lk + 2][lrow] = va.z; sA[0][lk + 3][lrow] = va.w;
        sB[0][lk + 0][lrow] = vb.x; sB[0][lk + 1][lrow] = vb.y;
        sB[0][lk + 2][lrow] = vb.z; sB[0][lk + 3][lrow] = vb.w;
    }
    __syncthreads();

    int buf = 0;
    for (int k0 = 0; k0 < KDIM; k0 += BKK, buf ^= 1) {
        float4 va, vb;
        bool has_next = (k0 + BKK < KDIM);
        if (has_next) {
            va = make_float4(0.f, 0.f, 0.f, 0.f);
            if (bm + lrow < M)
                va = *(const float4*)(A + (size_t)(bm + lrow) * KDIM + k0 + BKK + lk);
            vb = *(const float4*)(B + (size_t)(bn + lrow) * KDIM + k0 + BKK + lk);
        }

        #pragma unroll
        for (int kk = 0; kk < BKK; kk++) {
            float4 a0 = *(const float4*)&sA[buf][kk][ty * 4];
            float4 a1 = *(const float4*)&sA[buf][kk][64 + ty * 4];
            float4 b0 = *(const float4*)&sB[buf][kk][tx * 4];
            float4 b1 = *(const float4*)&sB[buf][kk][64 + tx * 4];
            float ar[8] = {a0.x, a0.y, a0.z, a0.w, a1.x, a1.y, a1.z, a1.w};
            float bc[8] = {b0.x, b0.y, b0.z, b0.w, b1.x, b1.y, b1.z, b1.w};
            #pragma unroll
            for (int i = 0; i < 8; i++)
                #pragma unroll
                for (int j = 0; j < 8; j++) acc[i][j] = fmaf(ar[i], bc[j], acc[i][j]);
        }

        if (has_next) {
            int nb = buf ^ 1;
            sA[nb][lk + 0][lrow] = va.x; sA[nb][lk + 1][lrow] = va.y;
            sA[nb][lk + 2][lrow] = va.z; sA[nb][lk + 3][lrow] = va.w;
            sB[nb][lk + 0][lrow] = vb.x; sB[nb][lk + 1][lrow] = vb.y;
            sB[nb][lk + 2][lrow] = vb.z; sB[nb][lk + 3][lrow] = vb.w;
            __syncthreads();
        }
    }

    #pragma unroll
    for (int ih = 0; ih < 2; ih++) {
        #pragma unroll
        for (int i = 0; i < 4; i++) {
            int m = bm + ih * 64 + ty * 4 + i;
            if (m >= M) continue;
            int ridx = ih * 4 + i;
            int bw = m / NSEQ, nn = m - bw * NSEQ;
            #pragma unroll
            for (int jh = 0; jh < 2; jh++) {
                int o = bn + jh * 64 + tx * 4;
                float4 v = make_float4(acc[ridx][jh * 4 + 0], acc[ridx][jh * 4 + 1],
                                       acc[ridx][jh * 4 + 2], acc[ridx][jh * 4 + 3]);
                if (MODE == 0) {
                    int part = o / DIMC;
                    int oc = o - part * DIMC;
                    int hh = oc >> 5, d = oc & 31;
                    if (part == 0) {
                        float4 b = *(const float4*)(bias0 + oc);
                        v.x += b.x; v.y += b.y; v.z += b.z; v.w += b.w;
                    } else if (part == 2) {
                        float4 b = *(const float4*)(bias1 + oc);
                        v.x += b.x; v.y += b.y; v.z += b.z; v.w += b.w;
                    }
                    size_t dst = ((size_t)(bw * NHEADS + hh) * NSEQ + nn) * HD + d;
                    float* tgt = (part == 0) ? g_Q : (part == 1 ? g_K : g_V);
                    *(float4*)(tgt + dst) = v;
                } else {
                    float4 b = *(const float4*)(bias0 + o);
                    v.x += b.x; v.y += b.y; v.z += b.z; v.w += b.w;
                    *(float4*)(Cout + (size_t)m * DIMC + o) = v;
                }
            }
        }
    }
}

// ---------------- kernel 4: windowed attention -----------------------------
// 512 threads/CTA, one per (64-q tile, head, window).
// smem: sQ 64x36, sK 343x36, sVT 32x348, sS 64x344; partials alias sQ/sK.
#define QT 64
#define QK_STR 36
#define VT_STR 348
#define SS_STR 344
#define PART_STR 33
#define ATTN_THREADS 512
#define SMEM_FLOATS (QT * QK_STR + NSEQ * QK_STR + HD * VT_STR + QT * SS_STR)

__global__ void __launch_bounds__(ATTN_THREADS, 1)
attn_kernel(const float* __restrict__ mask, const float* __restrict__ logit_scale) {
    extern __shared__ float smem[];
    float* sQ  = smem;                       // 64*36
    float* sK  = sQ + QT * QK_STR;           // 343*36
    float* sVT = sK + NSEQ * QK_STR;         // 32*348
    float* sS  = sVT + HD * VT_STR;          // 64*344
    float* sPart = sQ;                       // 4 * 64*33 = 8448 fl, aliases sQ+sK

    int qbase = blockIdx.x * QT;
    int h  = blockIdx.y;
    int bw = blockIdx.z;
    int tid = threadIdx.x;
    int warp = tid >> 5, lane = tid & 31;
    int qrows = min(QT, NSEQ - qbase);
    size_t headBase = ((size_t)(bw * NHEADS + h) * NSEQ) * HD;

    const float* Kg = g_K + headBase;
    const float* Vg = g_V + headBase;
    const float* Qg = g_Q + headBase + (size_t)qbase * HD;

    // ---- loads ----
    for (int e4 = tid; e4 < NSEQ * 8; e4 += ATTN_THREADS) {
        int r = e4 >> 3, d4 = (e4 & 7) * 4;
        float4 v = *(const float4*)(Kg + r * HD + d4);
        sK[r * QK_STR + d4 + 0] = v.x; sK[r * QK_STR + d4 + 1] = v.y;
        sK[r * QK_STR + d4 + 2] = v.z; sK[r * QK_STR + d4 + 3] = v.w;
    }
    for (int e = tid; e < NSEQ * HD; e += ATTN_THREADS) {
        int j = e >> 5, d = e & 31;
        sVT[d * VT_STR + j] = Vg[e];
    }
    if (tid < HD) sVT[tid * VT_STR + 343] = 0.f;
    for (int e4 = tid; e4 < qrows * 8; e4 += ATTN_THREADS) {
        int r = e4 >> 3, d4 = (e4 & 7) * 4;
        float4 v = *(const float4*)(Qg + r * HD + d4);
        sQ[r * QK_STR + d4 + 0] = v.x; sQ[r * QK_STR + d4 + 1] = v.y;
        sQ[r * QK_STR + d4 + 2] = v.z; sQ[r * QK_STR + d4 + 3] = v.w;
    }
    __syncthreads();

    // ---- cosine normalization ----
    for (int r = warp; r < NSEQ; r += 16) {
        float v = sK[r * QK_STR + lane];
        float s = warpSum(v * v);
        sK[r * QK_STR + lane] = v * (1.f / fmaxf(sqrtf(s), 1e-12f));
    }
    for (int r = warp; r < qrows; r += 16) {
        float v = sQ[r * QK_STR + lane];
        float s = warpSum(v * v);
        sQ[r * QK_STR + lane] = v * (1.f / fmaxf(sqrtf(s), 1e-12f));
    }
    __syncthreads();

    // ---- scores: 4x4 per thread, 64 x 128 tiles ----
    float scale = expf(fminf(logit_scale[h], 4.6051702f));
    {
        int tx = tid & 31;        // col lane
        int ty = tid >> 5;        // 0..15 -> rows ty*4..+3
        for (int c0 = 0; c0 < NSEQ; c0 += 128) {
            float acc[4][4];
            #pragma unroll
            for (int i = 0; i < 4; i++)
                #pragma unroll
                for (int j = 0; j < 4; j++) acc[i][j] = 0.f;
            int col[4];
            bool cv[4];
            #pragma unroll
            for (int k = 0; k < 4; k++) {
                col[k] = c0 + tx + 32 * k;
                cv[k] = col[k] < NSEQ;
            }
            #pragma unroll
            for (int d4 = 0; d4 < HD; d4 += 4) {
                float4 kf[4], qf[4];
                #pragma unroll
                for (int k = 0; k < 4; k++)
                    kf[k] = cv[k] ? *(const float4*)&sK[col[k] * QK_STR + d4]
                                  : make_float4(0.f, 0.f, 0.f, 0.f);
                #pragma unroll
                for (int i = 0; i < 4; i++)
                    qf[i] = *(const float4*)&sQ[(ty * 4 + i) * QK_STR + d4];
                #pragma unroll
                for (int i = 0; i < 4; i++)
                    #pragma unroll
                    for (int k = 0; k < 4; k++) {
                        acc[i][k] = fmaf(qf[i].x, kf[k].x, acc[i][k]);
                        acc[i][k] = fmaf(qf[i].y, kf[k].y, acc[i][k]);
                        acc[i][k] = fmaf(qf[i].z, kf[k].z, acc[i][k]);
                        acc[i][k] = fmaf(qf[i].w, kf[k].w, acc[i][k]);
                    }
            }
            #pragma unroll
            for (int i = 0; i < 4; i++) {
                int gi = qbase + ty * 4 + i;
                if (gi >= NSEQ) continue;
                size_t bofs = ((size_t)h * NSEQ + gi) * NSEQ;
                size_t mofs = ((size_t)bw * NSEQ + gi) * NSEQ;
                #pragma unroll
                for (int k = 0; k < 4; k++) {
                    if (!cv[k]) continue;
                    sS[(ty * 4 + i) * SS_STR + col[k]] =
                        fmaf(acc[i][k], scale, g_bias[bofs + col[k]] + mask[mofs + col[k]]);
                }
            }
        }
    }
    __syncthreads();

    // ---- softmax ----
    for (int r = warp; r < QT; r += 16) {
        if (qbase + r >= NSEQ) continue;
        float* row = sS + r * SS_STR;
        float m = -1e30f;
        for (int j = lane; j < NSEQ; j += 32) m = fmaxf(m, row[j]);
        m = warpMax(m);
        float sum = 0.f;
        for (int j = lane; j < NSEQ; j += 32) {
            float p = __expf(row[j] - m);
            row[j] = p;
            sum += p;
        }
        sum = warpSum(sum);
        float inv = 1.f / sum;
        for (int j = lane; j < NSEQ; j += 32) row[j] *= inv;
        if (lane == 0) row[343] = 0.f;
    }
    __syncthreads();

    // ---- O = P @ V : 4x4 per thread, j split 4 ways ----
    {
        int js  = tid >> 7;         // 0..3
        int ty2 = (tid >> 3) & 15;  // rows ty2 + 16*i
        int cx2 = tid & 7;          // cols cx2 + 8*c
        float acc[4][4];
        #pragma unroll
        for (int i = 0; i < 4; i++)
            #pragma unroll
            for (int c = 0; c < 4; c++) acc[i][c] = 0.f;
        for (int jj = js; jj < 86; jj += 4) {
            int j4 = jj * 4;
            float4 pf[4], vf[4];
            #pragma unroll
            for (int i = 0; i < 4; i++)
                pf[i] = *(const float4*)&sS[(ty2 + 16 * i) * SS_STR + j4];
            #pragma unroll
            for (int c = 0; c < 4; c++)
                vf[c] = *(const float4*)&sVT[(cx2 + 8 * c) * VT_STR + j4];
            #pragma unroll
            for (int i = 0; i < 4; i++)
                #pragma unroll
                for (int c = 0; c < 4; c++) {
                    acc[i][c] = fmaf(pf[i].x, vf[c].x, acc[i][c]);
                    acc[i][c] = fmaf(pf[i].y, vf[c].y, acc[i][c]);
                    acc[i][c] = fmaf(pf[i].z, vf[c].z, acc[i][c]);
                    acc[i][c] = fmaf(pf[i].w, vf[c].w, acc[i][c]);
                }
        }
        __syncthreads();   // sQ/sK dead; partials may alias now
        #pragma unroll
        for (int i = 0; i < 4; i++)
            #pragma unroll
            for (int c = 0; c < 4; c++)
                sPart[js * (QT * PART_STR) + (ty2 + 16 * i) * PART_STR + (cx2 + 8 * c)] = acc[i][c];
        __syncthreads();
        for (int o = tid; o < QT * HD; o += ATTN_THREADS) {
            int row = o >> 5, cc = o & 31;
            int gi = qbase + row;
            if (gi >= NSEQ) continue;
            float s = sPart[row * PART_STR + cc]
                    + sPart[1 * (QT * PART_STR) + row * PART_STR + cc]
                    + sPart[2 * (QT * PART_STR) + row * PART_STR + cc]
                    + sPart[3 * (QT * PART_STR) + row * PART_STR + cc];
            g_O[((size_t)bw * NSEQ + gi) * DIMC + h * HD + cc] = s;
        }
    }
}

// ---------------- launch -----------------------------------------------------
extern "C" void kernel_launch(void* const* d_in, const int* in_sizes, int n_in,
                              void* d_out, int out_size) {
    const float* x        = (const float*)d_in[0];
    const float* mask     = (const float*)d_in[1];
    const float* qkv_w    = (const float*)d_in[2];
    const float* q_bias   = (const float*)d_in[3];
    const float* v_bias   = (const float*)d_in[4];
    const float* lscale   = (const float*)d_in[5];
    const float* cpb_w1   = (const float*)d_in[6];
    const float* cpb_b1   = (const float*)d_in[7];
    const float* cpb_w2   = (const float*)d_in[8];
    const float* proj_w   = (const float*)d_in[9];
    const float* proj_b   = (const float*)d_in[10];
    const float* rel_tab  = (const float*)d_in[11];
    const int*   rel_idx  = (const int*)d_in[12];
    float* out = (float*)d_out;

    const int M = BATCH * NSEQ;   // 21952

    cpb_table_kernel<<<TABSZ, CPBH>>>(rel_tab, cpb_w1, cpb_b1, cpb_w2);

    {
        int total = NHEADS * NSEQ * NSEQ;
        bias_gather_kernel<<<(total + 255) / 256, 256>>>(rel_idx);
    }

    {
        dim3 grid((M + BM - 1) / BM, QKV_N / BN);
        sgemm_kernel<0><<<grid, 256>>>(x, qkv_w, q_bias, v_bias, nullptr, M);
    }

    {
        static const size_t smemBytes = (size_t)SMEM_FLOATS * sizeof(float);
        cudaFuncSetAttribute(attn_kernel,
                             cudaFuncAttributeMaxDynamicSharedMemorySize,
                             (int)smemBytes);
        dim3 grid((NSEQ + QT - 1) / QT, NHEADS, BATCH);
        attn_kernel<<<grid, ATTN_THREADS, smemBytes>>>(mask, lscale);
    }

    {
        dim3 grid((M + BM - 1) / BM, DIMC / BN);
        sgemm_kernel<1><<<grid, 256>>>(nullptr, proj_w, proj_b, nullptr, out, M);
    }
}

// round 5
// speedup vs baseline: 1.5107x; 1.1110x over previous
#include <cuda_runtime.h>
#include <cuda_bf16.h>
#include <math.h>
#include <stdint.h>

// ---------------- problem constants ----------------
#define BATCH   64
#define NSEQ    343
#define DIMC    384
#define NHEADS  12
#define HD      32
#define KDIM    384
#define QKV_N   1152
#define TABSZ   2197
#define CPBH    512
#define MTOT    (BATCH * NSEQ)      // 21952

// ---------------- scratch ----------------
__device__ float g_Q[(size_t)BATCH * NHEADS * NSEQ * HD];
__device__ float g_K[(size_t)BATCH * NHEADS * NSEQ * HD];
__device__ float g_V[(size_t)BATCH * NHEADS * NSEQ * HD];
__device__ float g_bias[(size_t)NHEADS * NSEQ * NSEQ];
__device__ float g_tableH[(size_t)TABSZ * NHEADS];

__device__ __nv_bfloat16 g_xhi[(size_t)MTOT * KDIM];
__device__ __nv_bfloat16 g_xlo[(size_t)MTOT * KDIM];
__device__ __nv_bfloat16 g_wqhi[(size_t)QKV_N * KDIM];
__device__ __nv_bfloat16 g_wqlo[(size_t)QKV_N * KDIM];
__device__ __nv_bfloat16 g_pwhi[(size_t)DIMC * KDIM];
__device__ __nv_bfloat16 g_pwlo[(size_t)DIMC * KDIM];
__device__ __nv_bfloat16 g_Ohi[(size_t)MTOT * DIMC];
__device__ __nv_bfloat16 g_Olo[(size_t)MTOT * DIMC];

__device__ __forceinline__ float warpSum(float v) {
    #pragma unroll
    for (int o = 16; o > 0; o >>= 1) v += __shfl_xor_sync(0xffffffffu, v, o);
    return v;
}
__device__ __forceinline__ float warpMax(float v) {
    #pragma unroll
    for (int o = 16; o > 0; o >>= 1) v = fmaxf(v, __shfl_xor_sync(0xffffffffu, v, o));
    return v;
}

// ---------------- mma helpers ----------------
__device__ __forceinline__ void ldmatrix_x4(uint32_t& r0, uint32_t& r1,
                                            uint32_t& r2, uint32_t& r3, uint32_t addr) {
    asm volatile("ldmatrix.sync.aligned.m8n8.x4.shared.b16 {%0,%1,%2,%3}, [%4];"
        : "=r"(r0), "=r"(r1), "=r"(r2), "=r"(r3) : "r"(addr));
}
__device__ __forceinline__ void mma_bf16(float* c, const uint32_t* a, const uint32_t* b) {
    asm volatile("mma.sync.aligned.m16n8k16.row.col.f32.bf16.bf16.f32 "
        "{%0,%1,%2,%3}, {%4,%5,%6,%7}, {%8,%9}, {%0,%1,%2,%3};"
        : "+f"(c[0]), "+f"(c[1]), "+f"(c[2]), "+f"(c[3])
        : "r"(a[0]), "r"(a[1]), "r"(a[2]), "r"(a[3]), "r"(b[0]), "r"(b[1]));
}

// ---------------- split kernels: fp32 -> bf16 hi + lo ----------------
// DST: 0 = x, 1 = qkv_w, 2 = proj_w. Dst arrays resolved in device code.
template <int DST>
__global__ void split_kernel(const float* __restrict__ src, int n4) {
    __nv_bfloat16* hi = (DST == 0) ? g_xhi : (DST == 1) ? g_wqhi : g_pwhi;
    __nv_bfloat16* lo = (DST == 0) ? g_xlo : (DST == 1) ? g_wqlo : g_pwlo;
    int i = blockIdx.x * blockDim.x + threadIdx.x;
    if (i >= n4) return;
    float4 v = ((const float4*)src)[i];
    __nv_bfloat16 h0 = __float2bfloat16(v.x);
    __nv_bfloat16 h1 = __float2bfloat16(v.y);
    __nv_bfloat16 h2 = __float2bfloat16(v.z);
    __nv_bfloat16 h3 = __float2bfloat16(v.w);
    __nv_bfloat162* hp = (__nv_bfloat162*)(hi + i * 4);
    __nv_bfloat162* lp = (__nv_bfloat162*)(lo + i * 4);
    hp[0] = __nv_bfloat162(h0, h1);
    hp[1] = __nv_bfloat162(h2, h3);
    lp[0] = __nv_bfloat162(__float2bfloat16(v.x - __bfloat162float(h0)),
                           __float2bfloat16(v.y - __bfloat162float(h1)));
    lp[1] = __nv_bfloat162(__float2bfloat16(v.z - __bfloat162float(h2)),
                           __float2bfloat16(v.w - __bfloat162float(h3)));
}

// ---------------- kernel 1: CPB MLP ----------------
__global__ void cpb_table_kernel(const float* __restrict__ tab,
                                 const float* __restrict__ w1,
                                 const float* __restrict__ b1,
                                 const float* __restrict__ w2) {
    __shared__ float hid[CPBH];
    int r = blockIdx.x;
    int tid = threadIdx.x;
    float t0 = tab[r * 3 + 0], t1 = tab[r * 3 + 1], t2 = tab[r * 3 + 2];
    float h = fmaf(w1[tid * 3 + 0], t0,
              fmaf(w1[tid * 3 + 1], t1,
              fmaf(w1[tid * 3 + 2], t2, b1[tid])));
    hid[tid] = fmaxf(h, 0.f);
    __syncthreads();
    int warp = tid >> 5, lane = tid & 31;
    if (warp < NHEADS) {
        float s = 0.f;
        #pragma unroll
        for (int j = lane; j < CPBH; j += 32) s = fmaf(hid[j], w2[warp * CPBH + j], s);
        s = warpSum(s);
        if (lane == 0) g_tableH[r * NHEADS + warp] = s;
    }
}

// ---------------- kernel 2: bias gather ----------------
__global__ void bias_gather_kernel(const int* __restrict__ idx) {
    int t = blockIdx.x * blockDim.x + threadIdx.x;
    const int NN = NSEQ * NSEQ;
    if (t >= NHEADS * NN) return;
    int h = t / NN;
    int ij = t - h * NN;
    float v = g_tableH[idx[ij] * NHEADS + h];
    g_bias[t] = 16.f / (1.f + __expf(-v));
}

// ---------------- tensor-core GEMM: C = A @ B^T via bf16 split ------------
// 3 passes: Ahi*Bhi + Ahi*Blo + Alo*Bhi, fp32 accum.
// CTA 128x128, 8 warps of 64x32, k-chunks of 32.
// MODE 0: A=x split, B=qkv_w split, scatter epilogue -> g_Q/g_K/g_V (+bias)
// MODE 1: A=O split,  B=proj_w split, Cout = acc + bias0
#define GBM 128
#define GBN 128
#define GBK 32
#define TSTR 40
#define NPASS 3

template <int MODE>
__global__ void __launch_bounds__(256, 2)
mma_gemm_kernel(const float* __restrict__ bias0, const float* __restrict__ bias1,
                float* __restrict__ Cout, int M) {
    const __nv_bfloat16* Ahi = (MODE == 0) ? g_xhi : g_Ohi;
    const __nv_bfloat16* Alo = (MODE == 0) ? g_xlo : g_Olo;
    const __nv_bfloat16* Bhi = (MODE == 0) ? g_wqhi : g_pwhi;
    const __nv_bfloat16* Blo = (MODE == 0) ? g_wqlo : g_pwlo;
    const __nv_bfloat16* Apass[NPASS] = {Ahi, Ahi, Alo};
    const __nv_bfloat16* Bpass[NPASS] = {Bhi, Blo, Bhi};

    __shared__ __nv_bfloat16 sA[2][GBM * TSTR];
    __shared__ __nv_bfloat16 sB[2][GBN * TSTR];

    int tid = threadIdx.x;
    int lane = tid & 31;
    int warp = tid >> 5;
    int wm = warp >> 2;          // 0..1
    int wn = warp & 3;           // 0..3
    int bm = blockIdx.x * GBM;
    int bn = blockIdx.y * GBN;

    int lrow = tid >> 1;         // 0..127
    int lk16 = (tid & 1) * 16;   // 0 / 16

    const int NCH = NPASS * (KDIM / GBK);  // 36

    float acc[16][4];
    #pragma unroll
    for (int t = 0; t < 16; t++)
        #pragma unroll
        for (int j = 0; j < 4; j++) acc[t][j] = 0.f;

    uint32_t sAu = (uint32_t)__cvta_generic_to_shared(&sA[0][0]);
    uint32_t sBu = (uint32_t)__cvta_generic_to_shared(&sB[0][0]);
    const uint32_t bufBytesA = GBM * TSTR * 2;
    const uint32_t bufBytesB = GBN * TSTR * 2;

    // prologue: load chunk 0
    {
        const __nv_bfloat16* Ap = Apass[0];
        const __nv_bfloat16* Bp = Bpass[0];
        uint4 a0, a1, b0, b1;
        if (bm + lrow < M) {
            const uint4* p = (const uint4*)(Ap + (size_t)(bm + lrow) * KDIM + lk16);
            a0 = p[0]; a1 = p[1];
        } else { a0 = make_uint4(0, 0, 0, 0); a1 = a0; }
        const uint4* q = (const uint4*)(Bp + (size_t)(bn + lrow) * KDIM + lk16);
        b0 = q[0]; b1 = q[1];
        *(uint4*)&sA[0][lrow * TSTR + lk16] = a0;
        *(uint4*)&sA[0][lrow * TSTR + lk16 + 8] = a1;
        *(uint4*)&sB[0][lrow * TSTR + lk16] = b0;
        *(uint4*)&sB[0][lrow * TSTR + lk16 + 8] = b1;
    }
    __syncthreads();

    int buf = 0;
    for (int it = 0; it < NCH; it++, buf ^= 1) {
        uint4 a0, a1, b0, b1;
        bool has_next = (it + 1 < NCH);
        if (has_next) {
            int nit = it + 1;
            int pass = nit / (KDIM / GBK);
            int kc = (nit % (KDIM / GBK)) * GBK;
            const __nv_bfloat16* Ap = Apass[pass];
            const __nv_bfloat16* Bp = Bpass[pass];
            if (bm + lrow < M) {
                const uint4* p = (const uint4*)(Ap + (size_t)(bm + lrow) * KDIM + kc + lk16);
                a0 = p[0]; a1 = p[1];
            } else { a0 = make_uint4(0, 0, 0, 0); a1 = a0; }
            const uint4* q = (const uint4*)(Bp + (size_t)(bn + lrow) * KDIM + kc + lk16);
            b0 = q[0]; b1 = q[1];
        }

        // compute on current buffer
        uint32_t baseA = sAu + buf * bufBytesA;
        uint32_t baseB = sBu + buf * bufBytesB;
        #pragma unroll
        for (int ks = 0; ks < 2; ks++) {
            uint32_t af[4][4], bfr[4][2];
            #pragma unroll
            for (int mi = 0; mi < 4; mi++) {
                int row = wm * 64 + mi * 16 + (lane & 15);
                int kb = ks * 16 + ((lane >> 4) << 3);
                ldmatrix_x4(af[mi][0], af[mi][1], af[mi][2], af[mi][3],
                            baseA + (row * TSTR + kb) * 2);
            }
            #pragma unroll
            for (int bj = 0; bj < 2; bj++) {
                int nrow = wn * 32 + bj * 16 + (lane & 7) + ((lane >> 4) << 3);
                int kb = ks * 16 + (((lane >> 3) & 1) << 3);
                uint32_t r0, r1, r2, r3;
                ldmatrix_x4(r0, r1, r2, r3, baseB + (nrow * TSTR + kb) * 2);
                bfr[bj * 2][0] = r0; bfr[bj * 2][1] = r1;
                bfr[bj * 2 + 1][0] = r2; bfr[bj * 2 + 1][1] = r3;
            }
            #pragma unroll
            for (int mi = 0; mi < 4; mi++)
                #pragma unroll
                for (int nj = 0; nj < 4; nj++)
                    mma_bf16(acc[mi * 4 + nj], af[mi], bfr[nj]);
        }

        if (has_next) {
            int nb = buf ^ 1;
            __syncthreads();
            *(uint4*)&sA[nb][lrow * TSTR + lk16] = a0;
            *(uint4*)&sA[nb][lrow * TSTR + lk16 + 8] = a1;
            *(uint4*)&sB[nb][lrow * TSTR + lk16] = b0;
            *(uint4*)&sB[nb][lrow * TSTR + lk16 + 8] = b1;
            __syncthreads();
        }
    }

    // ---- epilogue ----
    #pragma unroll
    for (int mi = 0; mi < 4; mi++) {
        #pragma unroll
        for (int nj = 0; nj < 4; nj++) {
            int col = bn + wn * 32 + nj * 8 + ((lane & 3) << 1);
            float* cr = acc[mi * 4 + nj];
            #pragma unroll
            for (int half = 0; half < 2; half++) {
                int m = bm + wm * 64 + mi * 16 + (lane >> 2) + half * 8;
                if (m >= M) continue;
                float v0 = cr[half * 2 + 0];
                float v1 = cr[half * 2 + 1];
                if (MODE == 0) {
                    int part = col / DIMC;
                    int oc = col - part * DIMC;
                    int hh = oc >> 5, d = oc & 31;
                    if (part == 0) { v0 += bias0[oc]; v1 += bias0[oc + 1]; }
                    else if (part == 2) { v0 += bias1[oc]; v1 += bias1[oc + 1]; }
                    int bw = m / NSEQ, nn = m - bw * NSEQ;
                    size_t dst = ((size_t)(bw * NHEADS + hh) * NSEQ + nn) * HD + d;
                    float* tgt = (part == 0) ? g_Q : (part == 1 ? g_K : g_V);
                    *(float2*)(tgt + dst) = make_float2(v0, v1);
                } else {
                    v0 += bias0[col];
                    v1 += bias0[col + 1];
                    *(float2*)(Cout + (size_t)m * DIMC + col) = make_float2(v0, v1);
                }
            }
        }
    }
}

// ---------------- kernel 4: windowed attention -----------------------------
#define QT 64
#define QK_STR 36
#define VT_STR 348
#define SS_STR 344
#define PART_STR 33
#define ATTN_THREADS 512
#define SMEM_FLOATS (QT * QK_STR + NSEQ * QK_STR + HD * VT_STR + QT * SS_STR)

__global__ void __launch_bounds__(ATTN_THREADS, 1)
attn_kernel(const float* __restrict__ mask, const float* __restrict__ logit_scale) {
    extern __shared__ float smem[];
    float* sQ  = smem;
    float* sK  = sQ + QT * QK_STR;
    float* sVT = sK + NSEQ * QK_STR;
    float* sS  = sVT + HD * VT_STR;
    float* sPart = sQ;

    int qbase = blockIdx.x * QT;
    int h  = blockIdx.y;
    int bw = blockIdx.z;
    int tid = threadIdx.x;
    int warp = tid >> 5, lane = tid & 31;
    int qrows = min(QT, NSEQ - qbase);
    size_t headBase = ((size_t)(bw * NHEADS + h) * NSEQ) * HD;

    const float* Kg = g_K + headBase;
    const float* Vg = g_V + headBase;
    const float* Qg = g_Q + headBase + (size_t)qbase * HD;

    for (int e4 = tid; e4 < NSEQ * 8; e4 += ATTN_THREADS) {
        int r = e4 >> 3, d4 = (e4 & 7) * 4;
        float4 v = *(const float4*)(Kg + r * HD + d4);
        sK[r * QK_STR + d4 + 0] = v.x; sK[r * QK_STR + d4 + 1] = v.y;
        sK[r * QK_STR + d4 + 2] = v.z; sK[r * QK_STR + d4 + 3] = v.w;
    }
    for (int e = tid; e < NSEQ * HD; e += ATTN_THREADS) {
        int j = e >> 5, d = e & 31;
        sVT[d * VT_STR + j] = Vg[e];
    }
    if (tid < HD) sVT[tid * VT_STR + 343] = 0.f;
    for (int e4 = tid; e4 < qrows * 8; e4 += ATTN_THREADS) {
        int r = e4 >> 3, d4 = (e4 & 7) * 4;
        float4 v = *(const float4*)(Qg + r * HD + d4);
        sQ[r * QK_STR + d4 + 0] = v.x; sQ[r * QK_STR + d4 + 1] = v.y;
        sQ[r * QK_STR + d4 + 2] = v.z; sQ[r * QK_STR + d4 + 3] = v.w;
    }
    __syncthreads();

    for (int r = warp; r < NSEQ; r += 16) {
        float v = sK[r * QK_STR + lane];
        float s = warpSum(v * v);
        sK[r * QK_STR + lane] = v * (1.f / fmaxf(sqrtf(s), 1e-12f));
    }
    for (int r = warp; r < qrows; r += 16) {
        float v = sQ[r * QK_STR + lane];
        float s = warpSum(v * v);
        sQ[r * QK_STR + lane] = v * (1.f / fmaxf(sqrtf(s), 1e-12f));
    }
    __syncthreads();

    float scale = expf(fminf(logit_scale[h], 4.6051702f));
    {
        int tx = tid & 31;
        int ty = tid >> 5;
        for (int c0 = 0; c0 < NSEQ; c0 += 128) {
            float acc[4][4];
            #pragma unroll
            for (int i = 0; i < 4; i++)
                #pragma unroll
                for (int j = 0; j < 4; j++) acc[i][j] = 0.f;
            int col[4];
            bool cv[4];
            #pragma unroll
            for (int k = 0; k < 4; k++) {
                col[k] = c0 + tx + 32 * k;
                cv[k] = col[k] < NSEQ;
            }
            #pragma unroll
            for (int d4 = 0; d4 < HD; d4 += 4) {
                float4 kf[4], qf[4];
                #pragma unroll
                for (int k = 0; k < 4; k++)
                    kf[k] = cv[k] ? *(const float4*)&sK[col[k] * QK_STR + d4]
                                  : make_float4(0.f, 0.f, 0.f, 0.f);
                #pragma unroll
                for (int i = 0; i < 4; i++)
                    qf[i] = *(const float4*)&sQ[(ty * 4 + i) * QK_STR + d4];
                #pragma unroll
                for (int i = 0; i < 4; i++)
                    #pragma unroll
                    for (int k = 0; k < 4; k++) {
                        acc[i][k] = fmaf(qf[i].x, kf[k].x, acc[i][k]);
                        acc[i][k] = fmaf(qf[i].y, kf[k].y, acc[i][k]);
                        acc[i][k] = fmaf(qf[i].z, kf[k].z, acc[i][k]);
                        acc[i][k] = fmaf(qf[i].w, kf[k].w, acc[i][k]);
                    }
            }
            #pragma unroll
            for (int i = 0; i < 4; i++) {
                int gi = qbase + ty * 4 + i;
                if (gi >= NSEQ) continue;
                size_t bofs = ((size_t)h * NSEQ + gi) * NSEQ;
                size_t mofs = ((size_t)bw * NSEQ + gi) * NSEQ;
                #pragma unroll
                for (int k = 0; k < 4; k++) {
                    if (!cv[k]) continue;
                    sS[(ty * 4 + i) * SS_STR + col[k]] =
                        fmaf(acc[i][k], scale, g_bias[bofs + col[k]] + mask[mofs + col[k]]);
                }
            }
        }
    }
    __syncthreads();

    for (int r = warp; r < QT; r += 16) {
        if (qbase + r >= NSEQ) continue;
        float* row = sS + r * SS_STR;
        float m = -1e30f;
        for (int j = lane; j < NSEQ; j += 32) m = fmaxf(m, row[j]);
        m = warpMax(m);
        float sum = 0.f;
        for (int j = lane; j < NSEQ; j += 32) {
            float p = __expf(row[j] - m);
            row[j] = p;
            sum += p;
        }
        sum = warpSum(sum);
        float inv = 1.f / sum;
        for (int j = lane; j < NSEQ; j += 32) row[j] *= inv;
        if (lane == 0) row[343] = 0.f;
    }
    __syncthreads();

    {
        int js  = tid >> 7;
        int ty2 = (tid >> 3) & 15;
        int cx2 = tid & 7;
        float acc[4][4];
        #pragma unroll
        for (int i = 0; i < 4; i++)
            #pragma unroll
            for (int c = 0; c < 4; c++) acc[i][c] = 0.f;
        for (int jj = js; jj < 86; jj += 4) {
            int j4 = jj * 4;
            float4 pf[4], vf[4];
            #pragma unroll
            for (int i = 0; i < 4; i++)
                pf[i] = *(const float4*)&sS[(ty2 + 16 * i) * SS_STR + j4];
            #pragma unroll
            for (int c = 0; c < 4; c++)
                vf[c] = *(const float4*)&sVT[(cx2 + 8 * c) * VT_STR + j4];
            #pragma unroll
            for (int i = 0; i < 4; i++)
                #pragma unroll
                for (int c = 0; c < 4; c++) {
                    acc[i][c] = fmaf(pf[i].x, vf[c].x, acc[i][c]);
                    acc[i][c] = fmaf(pf[i].y, vf[c].y, acc[i][c]);
                    acc[i][c] = fmaf(pf[i].z, vf[c].z, acc[i][c]);
                    acc[i][c] = fmaf(pf[i].w, vf[c].w, acc[i][c]);
                }
        }
        __syncthreads();
        #pragma unroll
        for (int i = 0; i < 4; i++)
            #pragma unroll
            for (int c = 0; c < 4; c++)
                sPart[js * (QT * PART_STR) + (ty2 + 16 * i) * PART_STR + (cx2 + 8 * c)] = acc[i][c];
        __syncthreads();
        for (int o = tid; o < QT * HD; o += ATTN_THREADS) {
            int row = o >> 5, cc = o & 31;
            int gi = qbase + row;
            if (gi >= NSEQ) continue;
            float s = sPart[row * PART_STR + cc]
                    + sPart[1 * (QT * PART_STR) + row * PART_STR + cc]
                    + sPart[2 * (QT * PART_STR) + row * PART_STR + cc]
                    + sPart[3 * (QT * PART_STR) + row * PART_STR + cc];
            size_t oidx = ((size_t)bw * NSEQ + gi) * DIMC + h * HD + cc;
            __nv_bfloat16 hh = __float2bfloat16(s);
            g_Ohi[oidx] = hh;
            g_Olo[oidx] = __float2bfloat16(s - __bfloat162float(hh));
        }
    }
}

// ---------------- launch -----------------------------------------------------
extern "C" void kernel_launch(void* const* d_in, const int* in_sizes, int n_in,
                              void* d_out, int out_size) {
    const float* x        = (const float*)d_in[0];
    const float* mask     = (const float*)d_in[1];
    const float* qkv_w    = (const float*)d_in[2];
    const float* q_bias   = (const float*)d_in[3];
    const float* v_bias   = (const float*)d_in[4];
    const float* lscale   = (const float*)d_in[5];
    const float* cpb_w1   = (const float*)d_in[6];
    const float* cpb_b1   = (const float*)d_in[7];
    const float* cpb_w2   = (const float*)d_in[8];
    const float* proj_w   = (const float*)d_in[9];
    const float* proj_b   = (const float*)d_in[10];
    const float* rel_tab  = (const float*)d_in[11];
    const int*   rel_idx  = (const int*)d_in[12];
    float* out = (float*)d_out;

    const int M = MTOT;

    // splits
    {
        int n4 = M * KDIM / 4;
        split_kernel<0><<<(n4 + 255) / 256, 256>>>(x, n4);
        n4 = QKV_N * KDIM / 4;
        split_kernel<1><<<(n4 + 255) / 256, 256>>>(qkv_w, n4);
        n4 = DIMC * KDIM / 4;
        split_kernel<2><<<(n4 + 255) / 256, 256>>>(proj_w, n4);
    }

    cpb_table_kernel<<<TABSZ, CPBH>>>(rel_tab, cpb_w1, cpb_b1, cpb_w2);

    {
        int total = NHEADS * NSEQ * NSEQ;
        bias_gather_kernel<<<(total + 255) / 256, 256>>>(rel_idx);
    }

    // QKV GEMM (tensor cores)
    {
        dim3 grid((M + GBM - 1) / GBM, QKV_N / GBN);
        mma_gemm_kernel<0><<<grid, 256>>>(q_bias, v_bias, nullptr, M);
    }

    // attention
    {
        static const size_t smemBytes = (size_t)SMEM_FLOATS * sizeof(float);
        cudaFuncSetAttribute(attn_kernel,
                             cudaFuncAttributeMaxDynamicSharedMemorySize,
                             (int)smemBytes);
        dim3 grid((NSEQ + QT - 1) / QT, NHEADS, BATCH);
        attn_kernel<<<grid, ATTN_THREADS, smemBytes>>>(mask, lscale);
    }

    // projection GEMM (tensor cores)
    {
        dim3 grid((M + GBM - 1) / GBM, DIMC / GBN);
        mma_gemm_kernel<1><<<grid, 256>>>(proj_b, nullptr, out, M);
    }
}